// round 5
// baseline (speedup 1.0000x reference)
#include <cuda_runtime.h>
#include <math.h>

#define Bn   2
#define Sn   2048
#define Dn   512
#define Hn   8
#define DHn  64
#define HIDn 2048
#define TD3  1536
#define NROW (Bn*Sn)   /* 4096 */

// ---------------------------------------------------------------------------
// Scratch (static device globals — no runtime allocation)
// ---------------------------------------------------------------------------
__device__ float g_kqv[Bn*Sn*TD3];      // 25 MB  [B,S,3D] (k | q | v)
__device__ float g_ctx[Bn*Sn*Dn];       //  8 MB  attention context
__device__ float g_attnout[Bn*Sn*Dn];   //  8 MB  ctx @ out_w + b
__device__ float g_h[Bn*Sn*Dn];         //  8 MB  LN1 output
__device__ float g_ff[Bn*Sn*Dn];        //  8 MB  fc2 output
__device__ float g_fc1[Bn*Sn*HIDn];     // 33 MB  gelu(fc1) output
__device__ float g_m[Bn*Hn*Sn];         // softmax row max
__device__ float g_s[Bn*Hn*Sn];         // softmax row sum

__device__ __forceinline__ float gelu_exact(float x) {
    return 0.5f * x * (1.0f + erff(x * 0.70710678118654752f));
}

// ---------------------------------------------------------------------------
// Tiled fp32 GEMM:  C[M,N] = A[M,K] @ B[K,N] + bias[N]   (ACT=1 -> exact GELU)
// 64x64 tile, BK=16, 256 threads, 4x4 microtile, float4 smem reads.
// Requires M%64==0, N%64==0, K%16==0 (true for all call sites).
// ---------------------------------------------------------------------------
template<int ACT>
__global__ __launch_bounds__(256)
void sgemm_bias(const float* __restrict__ A, const float* __restrict__ Bm,
                const float* __restrict__ bias, float* __restrict__ C,
                int M, int N, int K)
{
    __shared__ float As[16][68];   // As[k][m] (transposed A tile, padded)
    __shared__ float Bs[16][64];   // Bs[k][n]

    const int tid = threadIdx.x;
    const int tx  = tid & 15, ty = tid >> 4;
    const int m0  = blockIdx.y << 6, n0 = blockIdx.x << 6;

    const int a_r = tid >> 2, a_c = (tid & 3) << 2;   // A tile: 64 rows x 16 k
    const int b_r = tid >> 4, b_c = (tid & 15) << 2;  // B tile: 16 k x 64 n

    const float* Ap = A  + (size_t)(m0 + a_r) * K + a_c;
    const float* Bp = Bm + (size_t)b_r * N + n0 + b_c;

    float acc[4][4] = {};

    for (int k0 = 0; k0 < K; k0 += 16) {
        float4 av = *(const float4*)(Ap + k0);
        float4 bv = *(const float4*)(Bp + (size_t)k0 * N);
        As[a_c+0][a_r] = av.x;
        As[a_c+1][a_r] = av.y;
        As[a_c+2][a_r] = av.z;
        As[a_c+3][a_r] = av.w;
        *(float4*)&Bs[b_r][b_c] = bv;
        __syncthreads();
        #pragma unroll
        for (int k = 0; k < 16; k++) {
            float4 a4 = *(const float4*)&As[k][ty << 2];
            float4 b4 = *(const float4*)&Bs[k][tx << 2];
            float ar[4] = {a4.x, a4.y, a4.z, a4.w};
            float br[4] = {b4.x, b4.y, b4.z, b4.w};
            #pragma unroll
            for (int i = 0; i < 4; i++)
                #pragma unroll
                for (int j = 0; j < 4; j++)
                    acc[i][j] = fmaf(ar[i], br[j], acc[i][j]);
        }
        __syncthreads();
    }

    float4 bi = *(const float4*)&bias[n0 + (tx << 2)];
    #pragma unroll
    for (int i = 0; i < 4; i++) {
        float4 c;
        c.x = acc[i][0] + bi.x;
        c.y = acc[i][1] + bi.y;
        c.z = acc[i][2] + bi.z;
        c.w = acc[i][3] + bi.w;
        if (ACT == 1) {
            c.x = gelu_exact(c.x); c.y = gelu_exact(c.y);
            c.z = gelu_exact(c.z); c.w = gelu_exact(c.w);
        }
        *(float4*)&C[(size_t)(m0 + (ty << 2) + i) * N + n0 + (tx << 2)] = c;
    }
}

// ---------------------------------------------------------------------------
// Attention pass 1: energy[b,h,q,k] = 0.125 * q.k + prev, written to d_out.
// Simultaneously computes per-row softmax max (g_m) and sum-of-exp (g_s)
// via online update, so attn probabilities are never materialized.
// One block = (b, h, 64 q-rows); loops over 32 key tiles of 64.
// ---------------------------------------------------------------------------
__global__ __launch_bounds__(256)
void attn_energy_kernel(const float* __restrict__ kqv,
                        const float* __restrict__ prev,
                        float* __restrict__ energy,
                        float* __restrict__ gm, float* __restrict__ gs)
{
    __shared__ float Qt[64][68];    // Qt[d][q]
    __shared__ float Kt[64][68];    // Kt[d][k]
    __shared__ float red[64][34];   // per-row (m,s) partials across 16 tx lanes

    const int b = blockIdx.z, h = blockIdx.y, q0 = blockIdx.x << 6;
    const int tid = threadIdx.x, tx = tid & 15, ty = tid >> 4;
    const int lr = tid >> 4, ld0 = (tid & 15) << 2;
    const int ebase = (b * Hn + h) * Sn;

    // Load Q tile transposed (q chunk at offset Dn within kqv row)
    #pragma unroll
    for (int r2 = 0; r2 < 4; r2++) {
        int qi = lr + (r2 << 4);
        float4 qv = *(const float4*)&kqv[(size_t)(b*Sn + q0 + qi)*TD3 + Dn + h*DHn + ld0];
        Qt[ld0+0][qi] = qv.x; Qt[ld0+1][qi] = qv.y;
        Qt[ld0+2][qi] = qv.z; Qt[ld0+3][qi] = qv.w;
    }

    float m[4], sAcc[4];
    #pragma unroll
    for (int i = 0; i < 4; i++) { m[i] = -INFINITY; sAcc[i] = 0.f; }

    for (int kt = 0; kt < Sn/64; kt++) {
        const int k0 = kt << 6;
        __syncthreads();
        #pragma unroll
        for (int r2 = 0; r2 < 4; r2++) {
            int ki = lr + (r2 << 4);
            float4 kv = *(const float4*)&kqv[(size_t)(b*Sn + k0 + ki)*TD3 + h*DHn + ld0];
            Kt[ld0+0][ki] = kv.x; Kt[ld0+1][ki] = kv.y;
            Kt[ld0+2][ki] = kv.z; Kt[ld0+3][ki] = kv.w;
        }
        __syncthreads();

        float acc[4][4] = {};
        #pragma unroll 16
        for (int d = 0; d < 64; d++) {
            float4 a4 = *(const float4*)&Qt[d][ty << 2];
            float4 b4 = *(const float4*)&Kt[d][tx << 2];
            float ar[4] = {a4.x, a4.y, a4.z, a4.w};
            float br[4] = {b4.x, b4.y, b4.z, b4.w};
            #pragma unroll
            for (int i = 0; i < 4; i++)
                #pragma unroll
                for (int j = 0; j < 4; j++)
                    acc[i][j] = fmaf(ar[i], br[j], acc[i][j]);
        }

        #pragma unroll
        for (int i = 0; i < 4; i++) {
            int q = q0 + (ty << 2) + i;
            size_t idx = (size_t)(ebase + q) * Sn + k0 + (tx << 2);
            float4 pv = *(const float4*)&prev[idx];
            float e0 = fmaf(acc[i][0], 0.125f, pv.x);
            float e1 = fmaf(acc[i][1], 0.125f, pv.y);
            float e2 = fmaf(acc[i][2], 0.125f, pv.z);
            float e3 = fmaf(acc[i][3], 0.125f, pv.w);
            *(float4*)&energy[idx] = make_float4(e0, e1, e2, e3);
            float lm = fmaxf(fmaxf(e0, e1), fmaxf(e2, e3));
            float mn = fmaxf(m[i], lm);
            sAcc[i] = sAcc[i] * __expf(m[i] - mn)
                    + __expf(e0 - mn) + __expf(e1 - mn)
                    + __expf(e2 - mn) + __expf(e3 - mn);
            m[i] = mn;
        }
    }

    // Reduce (m,s) across the 16 tx lanes that share each q-row
    #pragma unroll
    for (int i = 0; i < 4; i++) {
        red[(ty << 2) + i][2*tx]     = m[i];
        red[(ty << 2) + i][2*tx + 1] = sAcc[i];
    }
    __syncthreads();
    if (tid < 64) {
        float M = -INFINITY;
        #pragma unroll
        for (int j = 0; j < 16; j++) M = fmaxf(M, red[tid][2*j]);
        float S = 0.f;
        #pragma unroll
        for (int j = 0; j < 16; j++) S += red[tid][2*j + 1] * __expf(red[tid][2*j] - M);
        int o = ebase + q0 + tid;
        gm[o] = M; gs[o] = S;
    }
}

// ---------------------------------------------------------------------------
// Attention pass 2: ctx[b,q,h*64+d] = sum_k softmax(energy)[q,k] * v[k,d]
// p = exp(e - m) / s recomputed on the fly from the energy buffer.
// ---------------------------------------------------------------------------
__global__ __launch_bounds__(256)
void attn_av_kernel(const float* __restrict__ kqv,
                    const float* __restrict__ energy,
                    const float* __restrict__ gm, const float* __restrict__ gs,
                    float* __restrict__ ctx)
{
    __shared__ float Pt[64][68];   // Pt[k][q]
    __shared__ float Vs[64][64];   // Vs[k][d]

    const int b = blockIdx.z, h = blockIdx.y, q0 = blockIdx.x << 6;
    const int tid = threadIdx.x, tx = tid & 15, ty = tid >> 4;
    const int lr = tid >> 4, ld0 = (tid & 15) << 2;
    const int ebase = (b * Hn + h) * Sn;

    float rm[4], ris[4];
    #pragma unroll
    for (int r2 = 0; r2 < 4; r2++) {
        int o = ebase + q0 + lr + (r2 << 4);
        rm[r2]  = gm[o];
        ris[r2] = 1.0f / gs[o];
    }

    float acc[4][4] = {};

    for (int kt = 0; kt < Sn/64; kt++) {
        const int k0 = kt << 6;
        __syncthreads();
        #pragma unroll
        for (int r2 = 0; r2 < 4; r2++) {
            int qi = lr + (r2 << 4);
            size_t eidx = (size_t)(ebase + q0 + qi) * Sn + k0 + ld0;
            float4 ev = *(const float4*)&energy[eidx];
            Pt[ld0+0][qi] = __expf(ev.x - rm[r2]) * ris[r2];
            Pt[ld0+1][qi] = __expf(ev.y - rm[r2]) * ris[r2];
            Pt[ld0+2][qi] = __expf(ev.z - rm[r2]) * ris[r2];
            Pt[ld0+3][qi] = __expf(ev.w - rm[r2]) * ris[r2];

            int ki = lr + (r2 << 4);   // v chunk at offset 2*Dn
            float4 vv = *(const float4*)&kqv[(size_t)(b*Sn + k0 + ki)*TD3 + 2*Dn + h*DHn + ld0];
            *(float4*)&Vs[ki][ld0] = vv;
        }
        __syncthreads();

        #pragma unroll 16
        for (int kk = 0; kk < 64; kk++) {
            float4 a4 = *(const float4*)&Pt[kk][ty << 2];
            float4 b4 = *(const float4*)&Vs[kk][tx << 2];
            float ar[4] = {a4.x, a4.y, a4.z, a4.w};
            float br[4] = {b4.x, b4.y, b4.z, b4.w};
            #pragma unroll
            for (int i = 0; i < 4; i++)
                #pragma unroll
                for (int j = 0; j < 4; j++)
                    acc[i][j] = fmaf(ar[i], br[j], acc[i][j]);
        }
    }

    #pragma unroll
    for (int i = 0; i < 4; i++) {
        int q = q0 + (ty << 2) + i;
        *(float4*)&ctx[(size_t)(b*Sn + q)*Dn + h*DHn + (tx << 2)] =
            make_float4(acc[i][0], acc[i][1], acc[i][2], acc[i][3]);
    }
}

// ---------------------------------------------------------------------------
// Fused residual + LayerNorm: out = LN(a + b) * g + beta, one block per row.
// ---------------------------------------------------------------------------
__global__ __launch_bounds__(128)
void ln_kernel(const float* __restrict__ a, const float* __restrict__ b,
               const float* __restrict__ g, const float* __restrict__ beta,
               float* __restrict__ out)
{
    const int row = blockIdx.x, tid = threadIdx.x;
    const size_t base = (size_t)row * Dn + (tid << 2);

    float4 va = *(const float4*)&a[base];
    float4 vb = *(const float4*)&b[base];
    float v0 = va.x + vb.x, v1 = va.y + vb.y, v2 = va.z + vb.z, v3 = va.w + vb.w;

    float s = v0 + v1 + v2 + v3;
    float q = v0*v0 + v1*v1 + v2*v2 + v3*v3;
    #pragma unroll
    for (int o = 16; o; o >>= 1) {
        s += __shfl_xor_sync(0xffffffffu, s, o);
        q += __shfl_xor_sync(0xffffffffu, q, o);
    }
    __shared__ float ss[4], sq[4];
    const int w = tid >> 5, lane = tid & 31;
    if (!lane) { ss[w] = s; sq[w] = q; }
    __syncthreads();
    s = ss[0] + ss[1] + ss[2] + ss[3];
    q = sq[0] + sq[1] + sq[2] + sq[3];

    const float mu  = s * (1.0f / Dn);
    const float var = q * (1.0f / Dn) - mu * mu;
    const float r   = rsqrtf(var + 1e-5f);

    float4 vg = *(const float4*)&g[tid << 2];
    float4 vt = *(const float4*)&beta[tid << 2];
    float4 o4;
    o4.x = (v0 - mu) * r * vg.x + vt.x;
    o4.y = (v1 - mu) * r * vg.y + vt.y;
    o4.z = (v2 - mu) * r * vg.z + vt.z;
    o4.w = (v3 - mu) * r * vg.w + vt.w;
    *(float4*)&out[base] = o4;
}

// ---------------------------------------------------------------------------
// Launch
// ---------------------------------------------------------------------------
extern "C" void kernel_launch(void* const* d_in, const int* in_sizes, int n_in,
                              void* d_out, int out_size)
{
    (void)in_sizes; (void)n_in; (void)out_size;
    const float* x     = (const float*)d_in[0];
    const float* prev  = (const float*)d_in[1];
    const float* kqv_w = (const float*)d_in[2];
    const float* kqv_b = (const float*)d_in[3];
    const float* out_w = (const float*)d_in[4];
    const float* out_b = (const float*)d_in[5];
    const float* fc1_w = (const float*)d_in[6];
    const float* fc1_b = (const float*)d_in[7];
    const float* fc2_w = (const float*)d_in[8];
    const float* fc2_b = (const float*)d_in[9];
    const float* ln1_g = (const float*)d_in[10];
    const float* ln1_b = (const float*)d_in[11];
    const float* ln2_g = (const float*)d_in[12];
    const float* ln2_b = (const float*)d_in[13];

    float* out    = (float*)d_out;                      // [B,S,D]
    float* energy = out + (size_t)Bn * Sn * Dn;         // [B,H,S,S]

    float *kqv, *ctx, *attnout, *h, *ff, *fc1o, *gm, *gs;
    cudaGetSymbolAddress((void**)&kqv,     g_kqv);
    cudaGetSymbolAddress((void**)&ctx,     g_ctx);
    cudaGetSymbolAddress((void**)&attnout, g_attnout);
    cudaGetSymbolAddress((void**)&h,       g_h);
    cudaGetSymbolAddress((void**)&ff,      g_ff);
    cudaGetSymbolAddress((void**)&fc1o,    g_fc1);
    cudaGetSymbolAddress((void**)&gm,      g_m);
    cudaGetSymbolAddress((void**)&gs,      g_s);

    // 1. kqv = x @ kqv_w + kqv_b
    sgemm_bias<0><<<dim3(TD3/64, NROW/64), 256>>>(x, kqv_w, kqv_b, kqv, NROW, TD3, Dn);
    // 2. energy (-> d_out) + online softmax stats
    attn_energy_kernel<<<dim3(Sn/64, Hn, Bn), 256>>>(kqv, prev, energy, gm, gs);
    // 3. ctx = softmax(energy) @ v
    attn_av_kernel<<<dim3(Sn/64, Hn, Bn), 256>>>(kqv, energy, gm, gs, ctx);
    // 4. attnout = ctx @ out_w + out_b
    sgemm_bias<0><<<dim3(Dn/64, NROW/64), 256>>>(ctx, out_w, out_b, attnout, NROW, Dn, Dn);
    // 5. h = LN1(attnout + x)
    ln_kernel<<<NROW, 128>>>(attnout, x, ln1_g, ln1_b, h);
    // 6. fc1o = gelu(h @ fc1_w + fc1_b)
    sgemm_bias<1><<<dim3(HIDn/64, NROW/64), 256>>>(h, fc1_w, fc1_b, fc1o, NROW, HIDn, Dn);
    // 7. ff = fc1o @ fc2_w + fc2_b
    sgemm_bias<0><<<dim3(Dn/64, NROW/64), 256>>>(fc1o, fc2_w, fc2_b, ff, NROW, Dn, HIDn);
    // 8. out = LN2(ff + h)  -> d_out
    ln_kernel<<<NROW, 128>>>(ff, h, ln2_g, ln2_b, out);
}

// round 7
// speedup vs baseline: 1.5416x; 1.5416x over previous
#include <cuda_runtime.h>
#include <cstdint>
#include <math.h>

#define Bn   2
#define Sn   2048
#define Dn   512
#define Hn   8
#define DHn  64
#define HIDn 2048
#define TD3  1536
#define NROW (Bn*Sn)   /* 4096 */

// ---------------------------------------------------------------------------
// Scratch (static device globals — no runtime allocation)
// ---------------------------------------------------------------------------
__device__ float g_kqv[Bn*Sn*TD3];      // 25 MB  [B,S,3D] (k | q | v)
__device__ float g_ctx[Bn*Sn*Dn];       //  8 MB
__device__ float g_attnout[Bn*Sn*Dn];   //  8 MB
__device__ float g_h[Bn*Sn*Dn];         //  8 MB
__device__ float g_ff[Bn*Sn*Dn];        //  8 MB
__device__ float g_fc1[Bn*Sn*HIDn];     // 33 MB
__device__ float g_m[Bn*Hn*Sn];
__device__ float g_s[Bn*Hn*Sn];

__device__ __forceinline__ float gelu_exact(float x) {
    return 0.5f * x * (1.0f + erff(x * 0.70710678118654752f));
}

__device__ __forceinline__ float f2tf32(float x) {
    unsigned int u;
    asm("cvt.rna.tf32.f32 %0, %1;" : "=r"(u) : "f"(x));
    return __uint_as_float(u);
}
__device__ __forceinline__ float4 cvt4(float4 v) {
    float4 r;
    r.x = f2tf32(v.x); r.y = f2tf32(v.y); r.z = f2tf32(v.z); r.w = f2tf32(v.w);
    return r;
}

__device__ __forceinline__ void mma_tf32(float acc[4], const unsigned int a[4],
                                         const unsigned int b[2]) {
    asm volatile(
        "mma.sync.aligned.m16n8k8.row.col.f32.tf32.tf32.f32 "
        "{%0,%1,%2,%3}, {%4,%5,%6,%7}, {%8,%9}, {%0,%1,%2,%3};"
        : "+f"(acc[0]), "+f"(acc[1]), "+f"(acc[2]), "+f"(acc[3])
        : "r"(a[0]), "r"(a[1]), "r"(a[2]), "r"(a[3]), "r"(b[0]), "r"(b[1]));
}

// ---------------------------------------------------------------------------
// tf32 tensor-core GEMM: C[M,N] = A[M,K] @ B[K,N] + bias[N]  (ACT=1 -> GELU)
// 128x128 block tile, BK=16, 256 threads (8 warps, 2x4), warp tile 64x32,
// mma.sync.m16n8k8.tf32, double-buffered smem with register prefetch.
// Requires M%128==0, N%128==0, K%16==0 (true at all call sites).
// ---------------------------------------------------------------------------
template<int ACT>
__global__ __launch_bounds__(256)
void tf32_gemm(const float* __restrict__ A, const float* __restrict__ Bm,
               const float* __restrict__ bias, float* __restrict__ C,
               int M, int N, int K)
{
    __shared__ float As[2][128][20];   // [m][k], stride 20 -> conflict-free frag LDS
    __shared__ float Bs[2][16][136];   // [k][n], stride 136 -> conflict-free frag LDS

    const int tid  = threadIdx.x;
    const int lane = tid & 31, warp = tid >> 5;
    const int gid  = lane >> 2, tig = lane & 3;
    const int wm   = (warp & 1) << 6;      // 0 or 64
    const int wn   = (warp >> 1) << 5;     // 0,32,64,96
    const int m0   = blockIdx.y << 7, n0 = blockIdx.x << 7;

    const int ar = tid >> 2, ac = (tid & 3) << 2;   // A tile: 2x(64 rows) x 16k
    const int br = tid >> 4, bc = (tid & 15) << 2;  // B tile: 16k x 2x(64 cols)

    const float* Ap0 = A  + (size_t)(m0 + ar)      * K + ac;
    const float* Ap1 = A  + (size_t)(m0 + ar + 64) * K + ac;
    const float* Bp  = Bm + (size_t)br * N + n0 + bc;

    float acc[4][4][4] = {};
    float4 aR0, aR1, bR0, bR1;

    // prologue: load tile 0
    aR0 = *(const float4*)(Ap0);
    aR1 = *(const float4*)(Ap1);
    bR0 = *(const float4*)(Bp);
    bR1 = *(const float4*)(Bp + 64);
    *(float4*)&As[0][ar][ac]      = cvt4(aR0);
    *(float4*)&As[0][ar + 64][ac] = cvt4(aR1);
    *(float4*)&Bs[0][br][bc]      = cvt4(bR0);
    *(float4*)&Bs[0][br][bc + 64] = cvt4(bR1);
    __syncthreads();

    const int nk = K >> 4;
    int buf = 0;

    for (int it = 0; it < nk; ++it) {
        const bool more = (it + 1 < nk);
        if (more) {
            const size_t k_next = (size_t)(it + 1) << 4;
            aR0 = *(const float4*)(Ap0 + k_next);
            aR1 = *(const float4*)(Ap1 + k_next);
            bR0 = *(const float4*)(Bp + k_next * N);
            bR1 = *(const float4*)(Bp + k_next * N + 64);
        }

        #pragma unroll
        for (int ks = 0; ks < 16; ks += 8) {
            unsigned int af[4][4], bf[4][2];
            #pragma unroll
            for (int mi = 0; mi < 4; mi++) {
                const int m = wm + (mi << 4) + gid;
                af[mi][0] = __float_as_uint(As[buf][m    ][ks + tig]);
                af[mi][1] = __float_as_uint(As[buf][m + 8][ks + tig]);
                af[mi][2] = __float_as_uint(As[buf][m    ][ks + tig + 4]);
                af[mi][3] = __float_as_uint(As[buf][m + 8][ks + tig + 4]);
            }
            #pragma unroll
            for (int ni = 0; ni < 4; ni++) {
                const int n = wn + (ni << 3) + gid;
                bf[ni][0] = __float_as_uint(Bs[buf][ks + tig    ][n]);
                bf[ni][1] = __float_as_uint(Bs[buf][ks + tig + 4][n]);
            }
            #pragma unroll
            for (int mi = 0; mi < 4; mi++)
                #pragma unroll
                for (int ni = 0; ni < 4; ni++)
                    mma_tf32(acc[mi][ni], af[mi], bf[ni]);
        }

        if (more) {
            const int nb = buf ^ 1;
            *(float4*)&As[nb][ar][ac]      = cvt4(aR0);
            *(float4*)&As[nb][ar + 64][ac] = cvt4(aR1);
            *(float4*)&Bs[nb][br][bc]      = cvt4(bR0);
            *(float4*)&Bs[nb][br][bc + 64] = cvt4(bR1);
            __syncthreads();
            buf = nb;
        }
    }

    // epilogue: bias (+ GELU) + store. c0/c1 -> (row, col..col+1); c2/c3 -> row+8.
    #pragma unroll
    for (int mi = 0; mi < 4; mi++) {
        const int row = m0 + wm + (mi << 4) + gid;
        #pragma unroll
        for (int ni = 0; ni < 4; ni++) {
            const int col = n0 + wn + (ni << 3) + (tig << 1);
            float2 b2 = *(const float2*)&bias[col];
            float v0 = acc[mi][ni][0] + b2.x;
            float v1 = acc[mi][ni][1] + b2.y;
            float v2 = acc[mi][ni][2] + b2.x;
            float v3 = acc[mi][ni][3] + b2.y;
            if (ACT == 1) {
                v0 = gelu_exact(v0); v1 = gelu_exact(v1);
                v2 = gelu_exact(v2); v3 = gelu_exact(v3);
            }
            *(float2*)&C[(size_t)row * N + col]       = make_float2(v0, v1);
            *(float2*)&C[(size_t)(row + 8) * N + col] = make_float2(v2, v3);
        }
    }
}

// ---------------------------------------------------------------------------
// Attention pass 1: energy = 0.125*q.k + prev -> d_out, + online softmax stats
// ---------------------------------------------------------------------------
__global__ __launch_bounds__(256)
void attn_energy_kernel(const float* __restrict__ kqv,
                        const float* __restrict__ prev,
                        float* __restrict__ energy,
                        float* __restrict__ gm, float* __restrict__ gs)
{
    __shared__ float Qt[64][68];
    __shared__ float Kt[64][68];
    __shared__ float red[64][34];

    const int b = blockIdx.z, h = blockIdx.y, q0 = blockIdx.x << 6;
    const int tid = threadIdx.x, tx = tid & 15, ty = tid >> 4;
    const int lr = tid >> 4, ld0 = (tid & 15) << 2;
    const int ebase = (b * Hn + h) * Sn;

    #pragma unroll
    for (int r2 = 0; r2 < 4; r2++) {
        int qi = lr + (r2 << 4);
        float4 qv = *(const float4*)&kqv[(size_t)(b*Sn + q0 + qi)*TD3 + Dn + h*DHn + ld0];
        Qt[ld0+0][qi] = qv.x; Qt[ld0+1][qi] = qv.y;
        Qt[ld0+2][qi] = qv.z; Qt[ld0+3][qi] = qv.w;
    }

    float m[4], sAcc[4];
    #pragma unroll
    for (int i = 0; i < 4; i++) { m[i] = -INFINITY; sAcc[i] = 0.f; }

    for (int kt = 0; kt < Sn/64; kt++) {
        const int k0 = kt << 6;
        __syncthreads();
        #pragma unroll
        for (int r2 = 0; r2 < 4; r2++) {
            int ki = lr + (r2 << 4);
            float4 kv = *(const float4*)&kqv[(size_t)(b*Sn + k0 + ki)*TD3 + h*DHn + ld0];
            Kt[ld0+0][ki] = kv.x; Kt[ld0+1][ki] = kv.y;
            Kt[ld0+2][ki] = kv.z; Kt[ld0+3][ki] = kv.w;
        }
        __syncthreads();

        float acc[4][4] = {};
        #pragma unroll 16
        for (int d = 0; d < 64; d++) {
            float4 a4 = *(const float4*)&Qt[d][ty << 2];
            float4 b4 = *(const float4*)&Kt[d][tx << 2];
            float ar[4] = {a4.x, a4.y, a4.z, a4.w};
            float br[4] = {b4.x, b4.y, b4.z, b4.w};
            #pragma unroll
            for (int i = 0; i < 4; i++)
                #pragma unroll
                for (int j = 0; j < 4; j++)
                    acc[i][j] = fmaf(ar[i], br[j], acc[i][j]);
        }

        #pragma unroll
        for (int i = 0; i < 4; i++) {
            int q = q0 + (ty << 2) + i;
            size_t idx = (size_t)(ebase + q) * Sn + k0 + (tx << 2);
            float4 pv = *(const float4*)&prev[idx];
            float e0 = fmaf(acc[i][0], 0.125f, pv.x);
            float e1 = fmaf(acc[i][1], 0.125f, pv.y);
            float e2 = fmaf(acc[i][2], 0.125f, pv.z);
            float e3 = fmaf(acc[i][3], 0.125f, pv.w);
            *(float4*)&energy[idx] = make_float4(e0, e1, e2, e3);
            float lm = fmaxf(fmaxf(e0, e1), fmaxf(e2, e3));
            float mn = fmaxf(m[i], lm);
            sAcc[i] = sAcc[i] * __expf(m[i] - mn)
                    + __expf(e0 - mn) + __expf(e1 - mn)
                    + __expf(e2 - mn) + __expf(e3 - mn);
            m[i] = mn;
        }
    }

    #pragma unroll
    for (int i = 0; i < 4; i++) {
        red[(ty << 2) + i][2*tx]     = m[i];
        red[(ty << 2) + i][2*tx + 1] = sAcc[i];
    }
    __syncthreads();
    if (tid < 64) {
        float M = -INFINITY;
        #pragma unroll
        for (int j = 0; j < 16; j++) M = fmaxf(M, red[tid][2*j]);
        float S = 0.f;
        #pragma unroll
        for (int j = 0; j < 16; j++) S += red[tid][2*j + 1] * __expf(red[tid][2*j] - M);
        int o = ebase + q0 + tid;
        gm[o] = M; gs[o] = S;
    }
}

// ---------------------------------------------------------------------------
// Attention pass 2: ctx = softmax(energy) @ v  (p recomputed on the fly)
// ---------------------------------------------------------------------------
__global__ __launch_bounds__(256)
void attn_av_kernel(const float* __restrict__ kqv,
                    const float* __restrict__ energy,
                    const float* __restrict__ gm, const float* __restrict__ gs,
                    float* __restrict__ ctx)
{
    __shared__ float Pt[64][68];
    __shared__ float Vs[64][64];

    const int b = blockIdx.z, h = blockIdx.y, q0 = blockIdx.x << 6;
    const int tid = threadIdx.x, tx = tid & 15, ty = tid >> 4;
    const int lr = tid >> 4, ld0 = (tid & 15) << 2;
    const int ebase = (b * Hn + h) * Sn;

    float rm[4], ris[4];
    #pragma unroll
    for (int r2 = 0; r2 < 4; r2++) {
        int o = ebase + q0 + lr + (r2 << 4);
        rm[r2]  = gm[o];
        ris[r2] = 1.0f / gs[o];
    }

    float acc[4][4] = {};

    for (int kt = 0; kt < Sn/64; kt++) {
        const int k0 = kt << 6;
        __syncthreads();
        #pragma unroll
        for (int r2 = 0; r2 < 4; r2++) {
            int qi = lr + (r2 << 4);
            size_t eidx = (size_t)(ebase + q0 + qi) * Sn + k0 + ld0;
            float4 ev = *(const float4*)&energy[eidx];
            Pt[ld0+0][qi] = __expf(ev.x - rm[r2]) * ris[r2];
            Pt[ld0+1][qi] = __expf(ev.y - rm[r2]) * ris[r2];
            Pt[ld0+2][qi] = __expf(ev.z - rm[r2]) * ris[r2];
            Pt[ld0+3][qi] = __expf(ev.w - rm[r2]) * ris[r2];

            int ki = lr + (r2 << 4);
            float4 vv = *(const float4*)&kqv[(size_t)(b*Sn + k0 + ki)*TD3 + 2*Dn + h*DHn + ld0];
            *(float4*)&Vs[ki][ld0] = vv;
        }
        __syncthreads();

        #pragma unroll 16
        for (int kk = 0; kk < 64; kk++) {
            float4 a4 = *(const float4*)&Pt[kk][ty << 2];
            float4 b4 = *(const float4*)&Vs[kk][tx << 2];
            float ar[4] = {a4.x, a4.y, a4.z, a4.w};
            float br[4] = {b4.x, b4.y, b4.z, b4.w};
            #pragma unroll
            for (int i = 0; i < 4; i++)
                #pragma unroll
                for (int j = 0; j < 4; j++)
                    acc[i][j] = fmaf(ar[i], br[j], acc[i][j]);
        }
    }

    #pragma unroll
    for (int i = 0; i < 4; i++) {
        int q = q0 + (ty << 2) + i;
        *(float4*)&ctx[(size_t)(b*Sn + q)*Dn + h*DHn + (tx << 2)] =
            make_float4(acc[i][0], acc[i][1], acc[i][2], acc[i][3]);
    }
}

// ---------------------------------------------------------------------------
// Fused residual + LayerNorm
// ---------------------------------------------------------------------------
__global__ __launch_bounds__(128)
void ln_kernel(const float* __restrict__ a, const float* __restrict__ b,
               const float* __restrict__ g, const float* __restrict__ beta,
               float* __restrict__ out)
{
    const int row = blockIdx.x, tid = threadIdx.x;
    const size_t base = (size_t)row * Dn + (tid << 2);

    float4 va = *(const float4*)&a[base];
    float4 vb = *(const float4*)&b[base];
    float v0 = va.x + vb.x, v1 = va.y + vb.y, v2 = va.z + vb.z, v3 = va.w + vb.w;

    float s = v0 + v1 + v2 + v3;
    float q = v0*v0 + v1*v1 + v2*v2 + v3*v3;
    #pragma unroll
    for (int o = 16; o; o >>= 1) {
        s += __shfl_xor_sync(0xffffffffu, s, o);
        q += __shfl_xor_sync(0xffffffffu, q, o);
    }
    __shared__ float ss[4], sq[4];
    const int w = tid >> 5, lane = tid & 31;
    if (!lane) { ss[w] = s; sq[w] = q; }
    __syncthreads();
    s = ss[0] + ss[1] + ss[2] + ss[3];
    q = sq[0] + sq[1] + sq[2] + sq[3];

    const float mu  = s * (1.0f / Dn);
    const float var = q * (1.0f / Dn) - mu * mu;
    const float r   = rsqrtf(var + 1e-5f);

    float4 vg = *(const float4*)&g[tid << 2];
    float4 vt = *(const float4*)&beta[tid << 2];
    float4 o4;
    o4.x = (v0 - mu) * r * vg.x + vt.x;
    o4.y = (v1 - mu) * r * vg.y + vt.y;
    o4.z = (v2 - mu) * r * vg.z + vt.z;
    o4.w = (v3 - mu) * r * vg.w + vt.w;
    *(float4*)&out[base] = o4;
}

// ---------------------------------------------------------------------------
// Launch
// ---------------------------------------------------------------------------
extern "C" void kernel_launch(void* const* d_in, const int* in_sizes, int n_in,
                              void* d_out, int out_size)
{
    (void)in_sizes; (void)n_in; (void)out_size;
    const float* x     = (const float*)d_in[0];
    const float* prev  = (const float*)d_in[1];
    const float* kqv_w = (const float*)d_in[2];
    const float* kqv_b = (const float*)d_in[3];
    const float* out_w = (const float*)d_in[4];
    const float* out_b = (const float*)d_in[5];
    const float* fc1_w = (const float*)d_in[6];
    const float* fc1_b = (const float*)d_in[7];
    const float* fc2_w = (const float*)d_in[8];
    const float* fc2_b = (const float*)d_in[9];
    const float* ln1_g = (const float*)d_in[10];
    const float* ln1_b = (const float*)d_in[11];
    const float* ln2_g = (const float*)d_in[12];
    const float* ln2_b = (const float*)d_in[13];

    float* out    = (float*)d_out;                      // [B,S,D]
    float* energy = out + (size_t)Bn * Sn * Dn;         // [B,H,S,S]

    float *kqv, *ctx, *attnout, *h, *ff, *fc1o, *gm, *gs;
    cudaGetSymbolAddress((void**)&kqv,     g_kqv);
    cudaGetSymbolAddress((void**)&ctx,     g_ctx);
    cudaGetSymbolAddress((void**)&attnout, g_attnout);
    cudaGetSymbolAddress((void**)&h,       g_h);
    cudaGetSymbolAddress((void**)&ff,      g_ff);
    cudaGetSymbolAddress((void**)&fc1o,    g_fc1);
    cudaGetSymbolAddress((void**)&gm,      g_m);
    cudaGetSymbolAddress((void**)&gs,      g_s);

    // 1. kqv = x @ kqv_w + kqv_b            (tf32 tensor cores)
    tf32_gemm<0><<<dim3(TD3/128, NROW/128), 256>>>(x, kqv_w, kqv_b, kqv, NROW, TD3, Dn);
    // 2. energy (-> d_out) + online softmax stats
    attn_energy_kernel<<<dim3(Sn/64, Hn, Bn), 256>>>(kqv, prev, energy, gm, gs);
    // 3. ctx = softmax(energy) @ v
    attn_av_kernel<<<dim3(Sn/64, Hn, Bn), 256>>>(kqv, energy, gm, gs, ctx);
    // 4. attnout = ctx @ out_w + out_b      (tf32)
    tf32_gemm<0><<<dim3(Dn/128, NROW/128), 256>>>(ctx, out_w, out_b, attnout, NROW, Dn, Dn);
    // 5. h = LN1(attnout + x)
    ln_kernel<<<NROW, 128>>>(attnout, x, ln1_g, ln1_b, h);
    // 6. fc1o = gelu(h @ fc1_w + fc1_b)     (tf32 + fused GELU)
    tf32_gemm<1><<<dim3(HIDn/128, NROW/128), 256>>>(h, fc1_w, fc1_b, fc1o, NROW, HIDn, Dn);
    // 7. ff = fc1o @ fc2_w + fc2_b          (tf32)
    tf32_gemm<0><<<dim3(Dn/128, NROW/128), 256>>>(fc1o, fc2_w, fc2_b, ff, NROW, Dn, HIDn);
    // 8. out = LN2(ff + h)  -> d_out
    ln_kernel<<<NROW, 128>>>(ff, h, ln2_g, ln2_b, out);
}

// round 8
// speedup vs baseline: 2.2233x; 1.4422x over previous
#include <cuda_runtime.h>
#include <cstdint>
#include <math.h>

#define Bn   2
#define Sn   2048
#define Dn   512
#define Hn   8
#define DHn  64
#define HIDn 2048
#define TD3  1536
#define NROW (Bn*Sn)   /* 4096 */

// ---------------------------------------------------------------------------
// Scratch (static device globals — no runtime allocation)
// ---------------------------------------------------------------------------
__device__ float g_kqv[Bn*Sn*TD3];      // 25 MB  [B,S,3D] (k | q | v)
__device__ float g_ctx[Bn*Sn*Dn];       //  8 MB
__device__ float g_attnout[Bn*Sn*Dn];   //  8 MB
__device__ float g_h[Bn*Sn*Dn];         //  8 MB
__device__ float g_ff[Bn*Sn*Dn];        //  8 MB
__device__ float g_fc1[Bn*Sn*HIDn];     // 33 MB
__device__ float g_m[Bn*Hn*Sn];
__device__ float g_s[Bn*Hn*Sn];

__device__ __forceinline__ float gelu_exact(float x) {
    return 0.5f * x * (1.0f + erff(x * 0.70710678118654752f));
}

__device__ __forceinline__ float f2tf32(float x) {
    unsigned int u;
    asm("cvt.rna.tf32.f32 %0, %1;" : "=r"(u) : "f"(x));
    return __uint_as_float(u);
}
__device__ __forceinline__ float4 cvt4(float4 v) {
    float4 r;
    r.x = f2tf32(v.x); r.y = f2tf32(v.y); r.z = f2tf32(v.z); r.w = f2tf32(v.w);
    return r;
}

__device__ __forceinline__ void mma_tf32(float acc[4], const unsigned int a[4],
                                         const unsigned int b[2]) {
    asm volatile(
        "mma.sync.aligned.m16n8k8.row.col.f32.tf32.tf32.f32 "
        "{%0,%1,%2,%3}, {%4,%5,%6,%7}, {%8,%9}, {%0,%1,%2,%3};"
        : "+f"(acc[0]), "+f"(acc[1]), "+f"(acc[2]), "+f"(acc[3])
        : "r"(a[0]), "r"(a[1]), "r"(a[2]), "r"(a[3]), "r"(b[0]), "r"(b[1]));
}

// ---------------------------------------------------------------------------
// tf32 tensor-core GEMM: C[M,N] = A[M,K] @ B[K,N] + bias[N]  (ACT=1 -> GELU)
// 128x128 block tile, BK=16, 256 threads (8 warps, 2x4), warp tile 64x32.
// ---------------------------------------------------------------------------
template<int ACT>
__global__ __launch_bounds__(256)
void tf32_gemm(const float* __restrict__ A, const float* __restrict__ Bm,
               const float* __restrict__ bias, float* __restrict__ C,
               int M, int N, int K)
{
    __shared__ float As[2][128][20];
    __shared__ float Bs[2][16][136];

    const int tid  = threadIdx.x;
    const int lane = tid & 31, warp = tid >> 5;
    const int gid  = lane >> 2, tig = lane & 3;
    const int wm   = (warp & 1) << 6;
    const int wn   = (warp >> 1) << 5;
    const int m0   = blockIdx.y << 7, n0 = blockIdx.x << 7;

    const int ar = tid >> 2, ac = (tid & 3) << 2;
    const int br = tid >> 4, bc = (tid & 15) << 2;

    const float* Ap0 = A  + (size_t)(m0 + ar)      * K + ac;
    const float* Ap1 = A  + (size_t)(m0 + ar + 64) * K + ac;
    const float* Bp  = Bm + (size_t)br * N + n0 + bc;

    float acc[4][4][4] = {};
    float4 aR0, aR1, bR0, bR1;

    aR0 = *(const float4*)(Ap0);
    aR1 = *(const float4*)(Ap1);
    bR0 = *(const float4*)(Bp);
    bR1 = *(const float4*)(Bp + 64);
    *(float4*)&As[0][ar][ac]      = cvt4(aR0);
    *(float4*)&As[0][ar + 64][ac] = cvt4(aR1);
    *(float4*)&Bs[0][br][bc]      = cvt4(bR0);
    *(float4*)&Bs[0][br][bc + 64] = cvt4(bR1);
    __syncthreads();

    const int nk = K >> 4;
    int buf = 0;

    for (int it = 0; it < nk; ++it) {
        const bool more = (it + 1 < nk);
        if (more) {
            const size_t k_next = (size_t)(it + 1) << 4;
            aR0 = *(const float4*)(Ap0 + k_next);
            aR1 = *(const float4*)(Ap1 + k_next);
            bR0 = *(const float4*)(Bp + k_next * N);
            bR1 = *(const float4*)(Bp + k_next * N + 64);
        }

        #pragma unroll
        for (int ks = 0; ks < 16; ks += 8) {
            unsigned int af[4][4], bf[4][2];
            #pragma unroll
            for (int mi = 0; mi < 4; mi++) {
                const int m = wm + (mi << 4) + gid;
                af[mi][0] = __float_as_uint(As[buf][m    ][ks + tig]);
                af[mi][1] = __float_as_uint(As[buf][m + 8][ks + tig]);
                af[mi][2] = __float_as_uint(As[buf][m    ][ks + tig + 4]);
                af[mi][3] = __float_as_uint(As[buf][m + 8][ks + tig + 4]);
            }
            #pragma unroll
            for (int ni = 0; ni < 4; ni++) {
                const int n = wn + (ni << 3) + gid;
                bf[ni][0] = __float_as_uint(Bs[buf][ks + tig    ][n]);
                bf[ni][1] = __float_as_uint(Bs[buf][ks + tig + 4][n]);
            }
            #pragma unroll
            for (int mi = 0; mi < 4; mi++)
                #pragma unroll
                for (int ni = 0; ni < 4; ni++)
                    mma_tf32(acc[mi][ni], af[mi], bf[ni]);
        }

        if (more) {
            const int nb = buf ^ 1;
            *(float4*)&As[nb][ar][ac]      = cvt4(aR0);
            *(float4*)&As[nb][ar + 64][ac] = cvt4(aR1);
            *(float4*)&Bs[nb][br][bc]      = cvt4(bR0);
            *(float4*)&Bs[nb][br][bc + 64] = cvt4(bR1);
            __syncthreads();
            buf = nb;
        }
    }

    #pragma unroll
    for (int mi = 0; mi < 4; mi++) {
        const int row = m0 + wm + (mi << 4) + gid;
        #pragma unroll
        for (int ni = 0; ni < 4; ni++) {
            const int col = n0 + wn + (ni << 3) + (tig << 1);
            float2 b2 = *(const float2*)&bias[col];
            float v0 = acc[mi][ni][0] + b2.x;
            float v1 = acc[mi][ni][1] + b2.y;
            float v2 = acc[mi][ni][2] + b2.x;
            float v3 = acc[mi][ni][3] + b2.y;
            if (ACT == 1) {
                v0 = gelu_exact(v0); v1 = gelu_exact(v1);
                v2 = gelu_exact(v2); v3 = gelu_exact(v3);
            }
            *(float2*)&C[(size_t)row * N + col]       = make_float2(v0, v1);
            *(float2*)&C[(size_t)(row + 8) * N + col] = make_float2(v2, v3);
        }
    }
}

// ---------------------------------------------------------------------------
// Tensor-core attention pass 1:
//   energy[b,h,q,k] = 0.125 * (q . k) + prev  -> written to d_out region
//   plus per-row online softmax stats (gm = rowmax, gs = sum exp(e - gm)).
// Block = (b, h, 128 q-rows); loops over 16 key tiles of 128.
// Dynamic smem: Qs[128][68] | Ks[64][136] | redM[4*128] | redS[4*128]
// ---------------------------------------------------------------------------
#define SMEM_E ((128*68 + 64*136 + 2*4*128) * 4)

__global__ __launch_bounds__(256)
void attn_energy_tc(const float* __restrict__ kqv,
                    const float* __restrict__ prev,
                    float* __restrict__ energy,
                    float* __restrict__ gm, float* __restrict__ gs)
{
    extern __shared__ float sm[];
    float (*Qs)[68]  = (float(*)[68])sm;                       // [q][d]
    float (*Ks)[136] = (float(*)[136])(sm + 128*68);           // [d][k']
    float* redM = sm + 128*68 + 64*136;                        // [4][128]
    float* redS = redM + 4*128;

    const int b = blockIdx.z, h = blockIdx.y, q0 = blockIdx.x << 7;
    const int tid = threadIdx.x;
    const int lane = tid & 31, warp = tid >> 5;
    const int gid = lane >> 2, tig = lane & 3;
    const int wm = (warp & 1) << 6;      // 0 / 64
    const int wn = (warp >> 1) << 5;     // 0..96
    const int ebase = (b * Hn + h) * Sn;

    // Load Q tile [128 q][64 d] as tf32. 2 threads/row, 32 floats each.
    {
        const int qr = tid >> 1, qc = (tid & 1) << 5;
        const float* qrow = &kqv[(size_t)(b*Sn + q0 + qr)*TD3 + Dn + h*DHn + qc];
        #pragma unroll
        for (int i = 0; i < 8; i++)
            *(float4*)&Qs[qr][qc + (i << 2)] = cvt4(*(const float4*)(qrow + (i << 2)));
    }

    float mr[8], sr[8];
    #pragma unroll
    for (int r = 0; r < 8; r++) { mr[r] = -INFINITY; sr[r] = 0.f; }

    for (int kt = 0; kt < Sn/128; kt++) {
        const int k0 = kt << 7;
        __syncthreads();
        // Load K tile transposed -> Ks[d][k'] (tf32)
        {
            const int kr = tid >> 1, dc = (tid & 1) << 5;
            const float* krow = &kqv[(size_t)(b*Sn + k0 + kr)*TD3 + h*DHn + dc];
            #pragma unroll
            for (int i = 0; i < 8; i++) {
                float4 v = cvt4(*(const float4*)(krow + (i << 2)));
                const int d = dc + (i << 2);
                Ks[d+0][kr] = v.x; Ks[d+1][kr] = v.y;
                Ks[d+2][kr] = v.z; Ks[d+3][kr] = v.w;
            }
        }
        __syncthreads();

        float acc[4][4][4] = {};
        #pragma unroll
        for (int ks = 0; ks < 64; ks += 8) {
            unsigned int af[4][4], bf[4][2];
            #pragma unroll
            for (int mi = 0; mi < 4; mi++) {
                const int m = wm + (mi << 4) + gid;
                af[mi][0] = __float_as_uint(Qs[m    ][ks + tig]);
                af[mi][1] = __float_as_uint(Qs[m + 8][ks + tig]);
                af[mi][2] = __float_as_uint(Qs[m    ][ks + tig + 4]);
                af[mi][3] = __float_as_uint(Qs[m + 8][ks + tig + 4]);
            }
            #pragma unroll
            for (int ni = 0; ni < 4; ni++) {
                const int n = wn + (ni << 3) + gid;
                bf[ni][0] = __float_as_uint(Ks[ks + tig    ][n]);
                bf[ni][1] = __float_as_uint(Ks[ks + tig + 4][n]);
            }
            #pragma unroll
            for (int mi = 0; mi < 4; mi++)
                #pragma unroll
                for (int ni = 0; ni < 4; ni++)
                    mma_tf32(acc[mi][ni], af[mi], bf[ni]);
        }

        // Epilogue: e = 0.125*s + prev, store energy, online (m, sumexp)
        #pragma unroll
        for (int mi = 0; mi < 4; mi++) {
            const int rl = wm + (mi << 4) + gid;
            const size_t base0 = (size_t)(ebase + q0 + rl) * Sn + k0 + wn + (tig << 1);
            const size_t base1 = base0 + (size_t)8 * Sn;
            float v0[8], v1[8];
            float lm0 = -INFINITY, lm1 = -INFINITY;
            #pragma unroll
            for (int ni = 0; ni < 4; ni++) {
                float2 p0 = *(const float2*)&prev[base0 + (ni << 3)];
                float2 p1 = *(const float2*)&prev[base1 + (ni << 3)];
                float e00 = fmaf(acc[mi][ni][0], 0.125f, p0.x);
                float e01 = fmaf(acc[mi][ni][1], 0.125f, p0.y);
                float e10 = fmaf(acc[mi][ni][2], 0.125f, p1.x);
                float e11 = fmaf(acc[mi][ni][3], 0.125f, p1.y);
                *(float2*)&energy[base0 + (ni << 3)] = make_float2(e00, e01);
                *(float2*)&energy[base1 + (ni << 3)] = make_float2(e10, e11);
                v0[2*ni] = e00; v0[2*ni+1] = e01;
                v1[2*ni] = e10; v1[2*ni+1] = e11;
                lm0 = fmaxf(lm0, fmaxf(e00, e01));
                lm1 = fmaxf(lm1, fmaxf(e10, e11));
            }
            const int r0 = mi << 1, r1 = r0 + 1;
            float mn0 = fmaxf(mr[r0], lm0);
            float t0  = sr[r0] * __expf(mr[r0] - mn0);
            #pragma unroll
            for (int j = 0; j < 8; j++) t0 += __expf(v0[j] - mn0);
            sr[r0] = t0; mr[r0] = mn0;
            float mn1 = fmaxf(mr[r1], lm1);
            float t1  = sr[r1] * __expf(mr[r1] - mn1);
            #pragma unroll
            for (int j = 0; j < 8; j++) t1 += __expf(v1[j] - mn1);
            sr[r1] = t1; mr[r1] = mn1;
        }
    }

    // Reduce over the 4 tig lanes sharing each row
    #pragma unroll
    for (int r = 0; r < 8; r++) {
        #pragma unroll
        for (int off = 1; off <= 2; off <<= 1) {
            float mo = __shfl_xor_sync(0xffffffffu, mr[r], off);
            float so = __shfl_xor_sync(0xffffffffu, sr[r], off);
            float mn = fmaxf(mr[r], mo);
            sr[r] = sr[r] * __expf(mr[r] - mn) + so * __expf(mo - mn);
            mr[r] = mn;
        }
    }
    if (tig == 0) {
        const int wg = warp >> 1;
        #pragma unroll
        for (int mi = 0; mi < 4; mi++)
            #pragma unroll
            for (int j = 0; j < 2; j++) {
                const int rl = wm + (mi << 4) + (j << 3) + gid;
                redM[wg*128 + rl] = mr[(mi << 1) + j];
                redS[wg*128 + rl] = sr[(mi << 1) + j];
            }
    }
    __syncthreads();
    if (tid < 128) {
        float M = redM[tid];
        M = fmaxf(M, redM[128 + tid]);
        M = fmaxf(M, redM[256 + tid]);
        M = fmaxf(M, redM[384 + tid]);
        float S = redS[tid]       * __expf(redM[tid]       - M)
                + redS[128 + tid] * __expf(redM[128 + tid] - M)
                + redS[256 + tid] * __expf(redM[256 + tid] - M)
                + redS[384 + tid] * __expf(redM[384 + tid] - M);
        gm[ebase + q0 + tid] = M;
        gs[ebase + q0 + tid] = S;
    }
}

// ---------------------------------------------------------------------------
// Tensor-core attention pass 2: ctx = softmax(energy) @ v
// p recomputed on the fly from energy. Block = (b, h, 128 q) x 64 d.
// Dynamic smem: Ps[128][68] | Vs[64][72]
// ---------------------------------------------------------------------------
#define SMEM_AV ((128*68 + 64*72) * 4)

__global__ __launch_bounds__(256)
void attn_av_tc(const float* __restrict__ kqv,
                const float* __restrict__ energy,
                const float* __restrict__ gm, const float* __restrict__ gs,
                float* __restrict__ ctx)
{
    extern __shared__ float sm[];
    float (*Ps)[68] = (float(*)[68])sm;               // [q][k] probabilities
    float (*Vs)[72] = (float(*)[72])(sm + 128*68);    // [k][d]

    const int b = blockIdx.z, h = blockIdx.y, q0 = blockIdx.x << 7;
    const int tid = threadIdx.x;
    const int lane = tid & 31, warp = tid >> 5;
    const int gid = lane >> 2, tig = lane & 3;
    const int wm = (warp & 3) << 5;     // 0,32,64,96
    const int wn = (warp >> 2) << 5;    // 0,32
    const int ebase = (b * Hn + h) * Sn;

    // per-thread fixed row for the P-tile fill
    const int pr = tid >> 1, pc0 = (tid & 1) << 5;
    const float prm = gm[ebase + q0 + pr];
    const float pis = 1.0f / gs[ebase + q0 + pr];
    const float* erow = &energy[(size_t)(ebase + q0 + pr) * Sn + pc0];

    const int vr = tid >> 2, vc = (tid & 3) << 4;

    float acc[2][4][4] = {};

    for (int kt = 0; kt < Sn/64; kt++) {
        const int k0 = kt << 6;
        __syncthreads();
        // Fill P tile: p = exp(e - m) / s (tf32)
        #pragma unroll
        for (int i = 0; i < 8; i++) {
            float4 e = *(const float4*)(erow + k0 + (i << 2));
            float4 p;
            p.x = f2tf32(__expf(e.x - prm) * pis);
            p.y = f2tf32(__expf(e.y - prm) * pis);
            p.z = f2tf32(__expf(e.z - prm) * pis);
            p.w = f2tf32(__expf(e.w - prm) * pis);
            *(float4*)&Ps[pr][pc0 + (i << 2)] = p;
        }
        // Fill V tile [64 k][64 d] (no transpose needed)
        {
            const float* vrow = &kqv[(size_t)(b*Sn + k0 + vr)*TD3 + 2*Dn + h*DHn + vc];
            #pragma unroll
            for (int i = 0; i < 4; i++)
                *(float4*)&Vs[vr][vc + (i << 2)] = cvt4(*(const float4*)(vrow + (i << 2)));
        }
        __syncthreads();

        #pragma unroll
        for (int ks = 0; ks < 64; ks += 8) {
            unsigned int af[2][4], bf[4][2];
            #pragma unroll
            for (int mi = 0; mi < 2; mi++) {
                const int m = wm + (mi << 4) + gid;
                af[mi][0] = __float_as_uint(Ps[m    ][ks + tig]);
                af[mi][1] = __float_as_uint(Ps[m + 8][ks + tig]);
                af[mi][2] = __float_as_uint(Ps[m    ][ks + tig + 4]);
                af[mi][3] = __float_as_uint(Ps[m + 8][ks + tig + 4]);
            }
            #pragma unroll
            for (int ni = 0; ni < 4; ni++) {
                const int n = wn + (ni << 3) + gid;
                bf[ni][0] = __float_as_uint(Vs[ks + tig    ][n]);
                bf[ni][1] = __float_as_uint(Vs[ks + tig + 4][n]);
            }
            #pragma unroll
            for (int mi = 0; mi < 2; mi++)
                #pragma unroll
                for (int ni = 0; ni < 4; ni++)
                    mma_tf32(acc[mi][ni], af[mi], bf[ni]);
        }
    }

    #pragma unroll
    for (int mi = 0; mi < 2; mi++) {
        const int row = q0 + wm + (mi << 4) + gid;
        #pragma unroll
        for (int ni = 0; ni < 4; ni++) {
            const int col = h*DHn + wn + (ni << 3) + (tig << 1);
            *(float2*)&ctx[(size_t)(b*Sn + row)*Dn + col] =
                make_float2(acc[mi][ni][0], acc[mi][ni][1]);
            *(float2*)&ctx[(size_t)(b*Sn + row + 8)*Dn + col] =
                make_float2(acc[mi][ni][2], acc[mi][ni][3]);
        }
    }
}

// ---------------------------------------------------------------------------
// Fused residual + LayerNorm
// ---------------------------------------------------------------------------
__global__ __launch_bounds__(128)
void ln_kernel(const float* __restrict__ a, const float* __restrict__ b,
               const float* __restrict__ g, const float* __restrict__ beta,
               float* __restrict__ out)
{
    const int row = blockIdx.x, tid = threadIdx.x;
    const size_t base = (size_t)row * Dn + (tid << 2);

    float4 va = *(const float4*)&a[base];
    float4 vb = *(const float4*)&b[base];
    float v0 = va.x + vb.x, v1 = va.y + vb.y, v2 = va.z + vb.z, v3 = va.w + vb.w;

    float s = v0 + v1 + v2 + v3;
    float q = v0*v0 + v1*v1 + v2*v2 + v3*v3;
    #pragma unroll
    for (int o = 16; o; o >>= 1) {
        s += __shfl_xor_sync(0xffffffffu, s, o);
        q += __shfl_xor_sync(0xffffffffu, q, o);
    }
    __shared__ float ss[4], sq[4];
    const int w = tid >> 5, lane = tid & 31;
    if (!lane) { ss[w] = s; sq[w] = q; }
    __syncthreads();
    s = ss[0] + ss[1] + ss[2] + ss[3];
    q = sq[0] + sq[1] + sq[2] + sq[3];

    const float mu  = s * (1.0f / Dn);
    const float var = q * (1.0f / Dn) - mu * mu;
    const float r   = rsqrtf(var + 1e-5f);

    float4 vg = *(const float4*)&g[tid << 2];
    float4 vt = *(const float4*)&beta[tid << 2];
    float4 o4;
    o4.x = (v0 - mu) * r * vg.x + vt.x;
    o4.y = (v1 - mu) * r * vg.y + vt.y;
    o4.z = (v2 - mu) * r * vg.z + vt.z;
    o4.w = (v3 - mu) * r * vg.w + vt.w;
    *(float4*)&out[base] = o4;
}

// ---------------------------------------------------------------------------
// Launch
// ---------------------------------------------------------------------------
extern "C" void kernel_launch(void* const* d_in, const int* in_sizes, int n_in,
                              void* d_out, int out_size)
{
    (void)in_sizes; (void)n_in; (void)out_size;
    const float* x     = (const float*)d_in[0];
    const float* prev  = (const float*)d_in[1];
    const float* kqv_w = (const float*)d_in[2];
    const float* kqv_b = (const float*)d_in[3];
    const float* out_w = (const float*)d_in[4];
    const float* out_b = (const float*)d_in[5];
    const float* fc1_w = (const float*)d_in[6];
    const float* fc1_b = (const float*)d_in[7];
    const float* fc2_w = (const float*)d_in[8];
    const float* fc2_b = (const float*)d_in[9];
    const float* ln1_g = (const float*)d_in[10];
    const float* ln1_b = (const float*)d_in[11];
    const float* ln2_g = (const float*)d_in[12];
    const float* ln2_b = (const float*)d_in[13];

    float* out    = (float*)d_out;                      // [B,S,D]
    float* energy = out + (size_t)Bn * Sn * Dn;         // [B,H,S,S]

    float *kqv, *ctx, *attnout, *h, *ff, *fc1o, *gm, *gs;
    cudaGetSymbolAddress((void**)&kqv,     g_kqv);
    cudaGetSymbolAddress((void**)&ctx,     g_ctx);
    cudaGetSymbolAddress((void**)&attnout, g_attnout);
    cudaGetSymbolAddress((void**)&h,       g_h);
    cudaGetSymbolAddress((void**)&ff,      g_ff);
    cudaGetSymbolAddress((void**)&fc1o,    g_fc1);
    cudaGetSymbolAddress((void**)&gm,      g_m);
    cudaGetSymbolAddress((void**)&gs,      g_s);

    cudaFuncSetAttribute(attn_energy_tc,
                         cudaFuncAttributeMaxDynamicSharedMemorySize, SMEM_E);
    cudaFuncSetAttribute(attn_av_tc,
                         cudaFuncAttributeMaxDynamicSharedMemorySize, SMEM_AV);

    // 1. kqv = x @ kqv_w + kqv_b            (tf32)
    tf32_gemm<0><<<dim3(TD3/128, NROW/128), 256>>>(x, kqv_w, kqv_b, kqv, NROW, TD3, Dn);
    // 2. energy (-> d_out) + online softmax stats   (tf32 tensor cores)
    attn_energy_tc<<<dim3(Sn/128, Hn, Bn), 256, SMEM_E>>>(kqv, prev, energy, gm, gs);
    // 3. ctx = softmax(energy) @ v          (tf32 tensor cores)
    attn_av_tc<<<dim3(Sn/128, Hn, Bn), 256, SMEM_AV>>>(kqv, energy, gm, gs, ctx);
    // 4. attnout = ctx @ out_w + out_b      (tf32)
    tf32_gemm<0><<<dim3(Dn/128, NROW/128), 256>>>(ctx, out_w, out_b, attnout, NROW, Dn, Dn);
    // 5. h = LN1(attnout + x)
    ln_kernel<<<NROW, 128>>>(attnout, x, ln1_g, ln1_b, h);
    // 6. fc1o = gelu(h @ fc1_w + fc1_b)     (tf32 + fused GELU)
    tf32_gemm<1><<<dim3(HIDn/128, NROW/128), 256>>>(h, fc1_w, fc1_b, fc1o, NROW, HIDn, Dn);
    // 7. ff = fc1o @ fc2_w + fc2_b          (tf32)
    tf32_gemm<0><<<dim3(Dn/128, NROW/128), 256>>>(fc1o, fc2_w, fc2_b, ff, NROW, Dn, HIDn);
    // 8. out = LN2(ff + h)  -> d_out
    ln_kernel<<<NROW, 128>>>(ff, h, ln2_g, ln2_b, out);
}